// round 13
// baseline (speedup 1.0000x reference)
#include <cuda_runtime.h>
#include <cuda_fp16.h>
#include <cstdint>

#define NN 5120
#define NE 163840
#define TBLD 256
#define LAT 128
#define NG 64
#define NNEU 80
#define N2 6400
#define H1 12800

#define SK1 4     // GEMM1 split-K  (100 N-tiles x 4 = 400 CTAs, 3/SM occupancy)
#define SK2 8     // GEMM2 split-K  (50 N-tiles x 8 = 400 CTAs)

// ---------------- device scratch ----------------
__device__ int    g_deg[NN];
__device__ int    g_srclist[NN * 128];
__device__ float  g_dinv[NN];
__device__ __half g_h[NN * LAT];           // fp16 (x @ Wg)
__device__ __half g_z[NN * LAT];           // fp16 relu(GCN out)
__device__ __half g_gram[NG * N2];         // fp16 (A of GEMM1)
__device__ float  g_z2p[(size_t)SK1 * NG * H1];
__device__ __half g_z2[NG * H1];           // fp16 (A of GEMM2)
__device__ float  g_yp[(size_t)SK2 * NG * N2];

// ---------------- graph-side kernels ----------------
__global__ void k_zero() {
    int i = blockIdx.x * 256 + threadIdx.x;
    if (i < NN) g_deg[i] = 0;
}

__global__ void k_fill(const int* __restrict__ src, const int* __restrict__ dst) {
    int e = blockIdx.x * 256 + threadIdx.x;
    if (e >= NE) return;
    int d = dst[e];
    int slot = atomicAdd(&g_deg[d], 1);
    if (slot < 128) g_srclist[(d << 7) + slot] = src[e];
}

__global__ void k_dinv() {
    int i = blockIdx.x * 256 + threadIdx.x;
    if (i < NN) {
        int c = g_deg[i];
        g_dinv[i] = (c > 0) ? rsqrtf((float)c) : 0.0f;
    }
}

// one warp per node; h is fp16, 256 B/row (uint2 per lane = 4 halves)
__global__ void k_gather_z(const float* __restrict__ bg) {
    int w = (blockIdx.x * blockDim.x + threadIdx.x) >> 5;
    int lane = threadIdx.x & 31;
    if (w >= NN) return;
    int cnt = g_deg[w];
    if (cnt > 128) cnt = 128;
    const int* sl = g_srclist + (w << 7);
    float4 acc = make_float4(0.f, 0.f, 0.f, 0.f);
    #pragma unroll 4
    for (int e = 0; e < cnt; e++) {
        int s = sl[e];
        float wt = g_dinv[s];
        uint2 v = ((const uint2*)(g_h + ((size_t)s << 7)))[lane];
        float2 p0 = __half22float2(*(__half2*)&v.x);
        float2 p1 = __half22float2(*(__half2*)&v.y);
        acc.x += wt * p0.x; acc.y += wt * p0.y;
        acc.z += wt * p1.x; acc.w += wt * p1.y;
    }
    float dv = g_dinv[w];
    float4 bb = ((const float4*)bg)[lane];
    __half2 h0 = __floats2half2_rn(fmaxf(dv * acc.x + bb.x, 0.f),
                                   fmaxf(dv * acc.y + bb.y, 0.f));
    __half2 h1 = __floats2half2_rn(fmaxf(dv * acc.z + bb.z, 0.f),
                                   fmaxf(dv * acc.w + bb.w, 0.f));
    uint2 o; o.x = *(uint32_t*)&h0; o.y = *(uint32_t*)&h1;
    ((uint2*)(g_z + ((size_t)w << 7)))[lane] = o;
}

__global__ void k_gram() {
    __shared__ float zt[128][81];
    const int b = blockIdx.x;
    const int tid = threadIdx.x;
    #pragma unroll
    for (int i = 0; i < 10; i++) {
        int f = tid + i * 256;                 // 2560 = 80 rows x 32 quads
        int row = f >> 5, k4 = f & 31;
        uint2 v = ((const uint2*)(g_z + ((size_t)(b * NNEU + row) << 7)))[k4];
        float2 p0 = __half22float2(*(__half2*)&v.x);
        float2 p1 = __half22float2(*(__half2*)&v.y);
        zt[k4 * 4 + 0][row] = p0.x; zt[k4 * 4 + 1][row] = p0.y;
        zt[k4 * 4 + 2][row] = p1.x; zt[k4 * 4 + 3][row] = p1.y;
    }
    __syncthreads();
    const int tx = tid & 15, ty = tid >> 4;
    const int i0 = ty * 5, j0 = tx * 5;
    float acc[5][5];
    #pragma unroll
    for (int i = 0; i < 5; i++)
        #pragma unroll
        for (int j = 0; j < 5; j++) acc[i][j] = 0.f;
    #pragma unroll 4
    for (int k = 0; k < 128; k++) {
        float a[5], c[5];
        #pragma unroll
        for (int u = 0; u < 5; u++) { a[u] = zt[k][i0 + u]; c[u] = zt[k][j0 + u]; }
        #pragma unroll
        for (int i = 0; i < 5; i++)
            #pragma unroll
            for (int j = 0; j < 5; j++) acc[i][j] += a[i] * c[j];
    }
    __half* G = g_gram + b * N2;
    #pragma unroll
    for (int i = 0; i < 5; i++)
        #pragma unroll
        for (int j = 0; j < 5; j++)
            G[(i0 + i) * NNEU + j0 + j] = __float2half_rn(acc[i][j]);
}

// ---------------- mma helpers ----------------
__device__ __forceinline__ uint32_t smem_u32(const void* p) {
    return (uint32_t)__cvta_generic_to_shared(p);
}
__device__ __forceinline__ void cpa16(uint32_t dst, const void* src) {
    asm volatile("cp.async.cg.shared.global [%0], [%1], 16;" :: "r"(dst), "l"(src));
}
__device__ __forceinline__ uint32_t ldsu(uint32_t addr) {
    uint32_t v; asm volatile("ld.shared.b32 %0, [%1];" : "=r"(v) : "r"(addr)); return v;
}
__device__ __forceinline__ float ldsf(uint32_t addr) {
    float v; asm volatile("ld.shared.f32 %0, [%1];" : "=f"(v) : "r"(addr)); return v;
}
__device__ __forceinline__ uint32_t cvt2h(float hi, float lo) {
    uint32_t d;
    asm("cvt.rn.f16x2.f32 %0, %1, %2;" : "=r"(d) : "f"(hi), "f"(lo));
    return d;
}
__device__ __forceinline__ void hmma16(float* c, const uint32_t* a, uint32_t b0, uint32_t b1) {
    asm volatile(
        "mma.sync.aligned.m16n8k16.row.col.f32.f16.f16.f32 "
        "{%0,%1,%2,%3}, {%4,%5,%6,%7}, {%8,%9}, {%0,%1,%2,%3};"
        : "+f"(c[0]), "+f"(c[1]), "+f"(c[2]), "+f"(c[3])
        : "r"(a[0]), "r"(a[1]), "r"(a[2]), "r"(a[3]), "r"(b0), "r"(b1));
}
__device__ __forceinline__ void hmma(float* c, const uint32_t* a, uint32_t b0, uint32_t b1) {
    asm volatile(
        "mma.sync.aligned.m16n8k8.row.col.f32.tf32.tf32.f32 "
        "{%0,%1,%2,%3}, {%4,%5,%6,%7}, {%8,%9}, {%0,%1,%2,%3};"
        : "+f"(c[0]), "+f"(c[1]), "+f"(c[2]), "+f"(c[3])
        : "r"(a[0]), "r"(a[1]), "r"(a[2]), "r"(a[3]), "r"(b0), "r"(b1));
}

// ============ big-GEMM: fp16 A x fp32 B (cvt in regs), 3-stage, 3 CTAs/SM ============
// 128 threads / 4 warps, tile M=64 x N=128; warp = 4 m16 x 4 n8; K-chunk 32 (2 k16).
// A smem: half[64][40] (5120 B, banks 20g+t distinct);
// B smem: float[32][132] (16896 B, banks 8t+g distinct).
// Stage 22016 B; 3 stages = 66048 B -> 3 CTAs/SM (198 KB).
#define FA_BYTES 5120
#define FSBW 132
#define FSTAGE_B (FA_BYTES + 32 * FSBW * 4)   // 22016 bytes

__global__ __launch_bounds__(128, 3) void k_fgemm(
    const __half* __restrict__ A, const float* __restrict__ B,
    float* __restrict__ C, int lda, int ldb, int ldc, int ctot, long csplit)
{
    extern __shared__ char smemc[];
    const int tid = threadIdx.x, wid = tid >> 5, lane = tid & 31;
    const int g = lane >> 2, t = lane & 3;
    const int n0 = blockIdx.x * 128;
    const int c0 = (int)((long)ctot * blockIdx.z / gridDim.z);
    const int c1 = (int)((long)ctot * (blockIdx.z + 1) / gridDim.z);
    const int nch = c1 - c0;
    const __half* Ab = A + (size_t)c0 * 32;
    const float* Bb = B + (size_t)c0 * 32 * ldb + n0;
    const uint32_t sb = smem_u32(smemc);
    const int nb = wid * 32;                 // warp n-base

    auto prefetch = [&](int ck) {
        uint32_t as = sb + (ck % 3) * FSTAGE_B;
        uint32_t bs = as + FA_BYTES;
        const __half* Ag = Ab + ck * 32;
        #pragma unroll
        for (int q = 0; q < 2; q++) {        // A: 64 rows x 64B
            int idx = q * 128 + tid, r = idx >> 2, f = idx & 3;
            cpa16(as + r * 80 + f * 16, Ag + (size_t)r * lda + f * 8);
        }
        const float* Bg = Bb + (size_t)ck * 32 * ldb;
        #pragma unroll
        for (int q = 0; q < 8; q++) {        // B: 32 rows x 512B
            int idx = q * 128 + tid, r = idx >> 5, f = idx & 31;
            cpa16(bs + r * (FSBW * 4) + f * 16, Bg + (size_t)r * ldb + f * 4);
        }
        asm volatile("cp.async.commit_group;" ::: "memory");
    };

    float acc[4][4][4];
    #pragma unroll
    for (int mt = 0; mt < 4; mt++)
        #pragma unroll
        for (int nt = 0; nt < 4; nt++)
            #pragma unroll
            for (int r = 0; r < 4; r++) acc[mt][nt][r] = 0.f;

    prefetch(0); prefetch(1);                // nch >= 2 always

    for (int it = 0; it < nch; it++) {
        // committed = min(it+2, nch); pending allowed = committed - (it+1)
        if (it + 2 <= nch) {
            asm volatile("cp.async.wait_group 1;" ::: "memory");
        } else {
            asm volatile("cp.async.wait_group 0;" ::: "memory");
        }
        __syncthreads();
        uint32_t as = sb + (it % 3) * FSTAGE_B;
        uint32_t bs = as + FA_BYTES;
        #pragma unroll
        for (int s = 0; s < 2; s++) {        // two k16 steps per chunk
            uint32_t a[4][4];
            #pragma unroll
            for (int mt = 0; mt < 4; mt++) {
                uint32_t r0 = as + (16 * mt + g) * 80 + s * 32 + t * 4;
                a[mt][0] = ldsu(r0);
                a[mt][1] = ldsu(r0 + 8 * 80);
                a[mt][2] = ldsu(r0 + 16);
                a[mt][3] = ldsu(r0 + 8 * 80 + 16);
            }
            #pragma unroll
            for (int nt = 0; nt < 4; nt++) {
                uint32_t col = nb + 8 * nt + g;
                uint32_t bo = bs + ((16 * s + 2 * t) * FSBW + col) * 4;
                float f0 = ldsf(bo);
                float f1 = ldsf(bo + FSBW * 4);
                float f2 = ldsf(bo + 8 * FSBW * 4);
                float f3 = ldsf(bo + 9 * FSBW * 4);
                uint32_t b0 = cvt2h(f1, f0);
                uint32_t b1 = cvt2h(f3, f2);
                #pragma unroll
                for (int mt = 0; mt < 4; mt++) hmma16(acc[mt][nt], a[mt], b0, b1);
            }
        }
        __syncthreads();
        if (it + 2 < nch) prefetch(it + 2);  // writes stage (it+2)%3 == (it-1)%3: freed
    }

    float* Cb = C + (size_t)blockIdx.z * csplit + n0 + nb;
    #pragma unroll
    for (int mt = 0; mt < 4; mt++) {
        #pragma unroll
        for (int nt = 0; nt < 4; nt++) {
            float* p0 = Cb + (size_t)(16 * mt + g) * ldc + 8 * nt + 2 * t;
            p0[0] = acc[mt][nt][0]; p0[1] = acc[mt][nt][1];
            float* p1 = p0 + 8 * (size_t)ldc;
            p1[0] = acc[mt][nt][2]; p1[1] = acc[mt][nt][3];
        }
    }
}

// ============ 8-warp tf32 template (h-GEMM only; H=1 -> fp16 output) ============
template<int NT, int RA, int H>
__global__ __launch_bounds__(256, 2) void k_tgemm(
    const float* __restrict__ A, const float* __restrict__ B,
    float* __restrict__ C, int lda, int ldb, int ldc, int ctot, long csplit)
{
    constexpr int BN   = 64 * NT;
    constexpr int SBW  = BN + 8;
    constexpr int ABUF = 64 * 36;
    constexpr int BUF  = ABUF + 32 * SBW;
    extern __shared__ float smem[];
    const int tid = threadIdx.x, wid = tid >> 5, lane = tid & 31;
    const int g = lane >> 2, t = lane & 3;
    const int n0 = blockIdx.x * BN;
    const int m0 = blockIdx.y * 64;
    const int c0 = (int)((long)ctot * blockIdx.z / gridDim.z);
    const int c1 = (int)((long)ctot * (blockIdx.z + 1) / gridDim.z);
    const int nch = c1 - c0;
    const float* Ab = A + (size_t)m0 * lda + (size_t)c0 * 32;
    const float* Bb = B + (size_t)c0 * 32 * ldb + n0;
    const uint32_t sb = smem_u32(smem);
    const int nbw = wid * 8 * NT;

    auto prefetch = [&](int ck, int buf) {
        uint32_t as = sb + buf * BUF * 4;
        uint32_t bs = as + ABUF * 4;
        const float* Ag = Ab + ck * 32;
        #pragma unroll
        for (int q = 0; q < 2; q++) {
            int idx = q * 256 + tid, r = idx >> 3, f = idx & 7;
            cpa16(as + (r * 36 + f * 4) * 4, Ag + (size_t)r * lda + f * 4);
        }
        const float* Bg = Bb + (size_t)ck * 32 * ldb;
        #pragma unroll
        for (int q = 0; q < 2 * NT; q++) {
            int idx = q * 256 + tid, r = idx / (16 * NT), f = idx % (16 * NT);
            cpa16(bs + (r * SBW + f * 4) * 4, Bg + (size_t)r * ldb + f * 4);
        }
        asm volatile("cp.async.commit_group;" ::: "memory");
    };

    float acc[4][NT][4];
    #pragma unroll
    for (int mt = 0; mt < 4; mt++)
        #pragma unroll
        for (int nt = 0; nt < NT; nt++)
            #pragma unroll
            for (int r = 0; r < 4; r++) acc[mt][nt][r] = 0.f;

    prefetch(0, 0);
    for (int it = 0; it < nch; it++) {
        if (it + 1 < nch) {
            prefetch(it + 1, (it + 1) & 1);
            asm volatile("cp.async.wait_group 1;" ::: "memory");
        } else {
            asm volatile("cp.async.wait_group 0;" ::: "memory");
        }
        __syncthreads();
        uint32_t as = sb + (it & 1) * BUF * 4;
        uint32_t bs = as + ABUF * 4;
        #pragma unroll
        for (int ks = 0; ks < 4; ks++) {
            uint32_t a[4][4];
            #pragma unroll
            for (int mt = 0; mt < 4; mt++) {
                uint32_t r0 = as + ((16 * mt + g) * 36 + 8 * ks + t) * 4;
                a[mt][0] = ldsu(r0);
                a[mt][1] = ldsu(r0 + 8 * 36 * 4);
                a[mt][2] = ldsu(r0 + 16);
                a[mt][3] = ldsu(r0 + 8 * 36 * 4 + 16);
                if (RA) {
                    a[mt][0] += 0x1000u; a[mt][1] += 0x1000u;
                    a[mt][2] += 0x1000u; a[mt][3] += 0x1000u;
                }
            }
            #pragma unroll
            for (int nt = 0; nt < NT; nt++) {
                uint32_t bo = bs + ((8 * ks + t) * SBW + nbw + 8 * nt + g) * 4;
                uint32_t b0 = ldsu(bo) + 0x1000u;
                uint32_t b1 = ldsu(bo + 4 * SBW * 4) + 0x1000u;
                #pragma unroll
                for (int mt = 0; mt < 4; mt++) hmma(acc[mt][nt], a[mt], b0, b1);
            }
        }
        __syncthreads();
    }

    #pragma unroll
    for (int mt = 0; mt < 4; mt++) {
        #pragma unroll
        for (int nt = 0; nt < NT; nt++) {
            if (H) {
                __half* Cb = (__half*)C + (size_t)blockIdx.z * csplit +
                             (size_t)m0 * ldc + n0 + nbw;
                __half2 h0 = __floats2half2_rn(acc[mt][nt][0], acc[mt][nt][1]);
                __half2 h1 = __floats2half2_rn(acc[mt][nt][2], acc[mt][nt][3]);
                *(__half2*)(Cb + (size_t)(16 * mt + g) * ldc + 8 * nt + 2 * t) = h0;
                *(__half2*)(Cb + (size_t)(16 * mt + g + 8) * ldc + 8 * nt + 2 * t) = h1;
            } else {
                float* Cb = C + (size_t)blockIdx.z * csplit + (size_t)m0 * ldc + n0 + nbw;
                float* p0 = Cb + (size_t)(16 * mt + g) * ldc + 8 * nt + 2 * t;
                p0[0] = acc[mt][nt][0]; p0[1] = acc[mt][nt][1];
                float* p1 = p0 + 8 * (size_t)ldc;
                p1[0] = acc[mt][nt][2]; p1[1] = acc[mt][nt][3];
            }
        }
    }
}

// combine SK1 GEMM1 partials + bias, relu -> fp16 g_z2
__global__ void k_relu_c(const float* __restrict__ b1) {
    int i = blockIdx.x * 256 + threadIdx.x;          // float4 idx < 204800
    const float4* P = (const float4*)g_z2p;
    float4 a = P[i];
    #pragma unroll
    for (int s = 1; s < SK1; s++) {
        float4 tv = P[(size_t)s * 204800 + i];
        a.x += tv.x; a.y += tv.y; a.z += tv.z; a.w += tv.w;
    }
    float4 bb = ((const float4*)b1)[i % 3200];
    __half2 h0 = __floats2half2_rn(fmaxf(a.x + bb.x, 0.f), fmaxf(a.y + bb.y, 0.f));
    __half2 h1 = __floats2half2_rn(fmaxf(a.z + bb.z, 0.f), fmaxf(a.w + bb.w, 0.f));
    ((__half2*)g_z2)[2 * i]     = h0;
    ((__half2*)g_z2)[2 * i + 1] = h1;
}

// combine SK2 GEMM2 partials + bias, sigmoid -> out
__global__ void k_sig_c(const float* __restrict__ b2, float* __restrict__ out) {
    int i = blockIdx.x * 256 + threadIdx.x;          // float4 idx < 102400
    const float4* P = (const float4*)g_yp;
    float4 a = P[i];
    #pragma unroll
    for (int p = 1; p < SK2; p++) {
        float4 tv = P[(size_t)p * 102400 + i];
        a.x += tv.x; a.y += tv.y; a.z += tv.z; a.w += tv.w;
    }
    float4 bb = ((const float4*)b2)[i % 1600];
    a.x = 1.f / (1.f + expf(-(a.x + bb.x)));
    a.y = 1.f / (1.f + expf(-(a.y + bb.y)));
    a.z = 1.f / (1.f + expf(-(a.z + bb.z)));
    a.w = 1.f / (1.f + expf(-(a.w + bb.w)));
    ((float4*)out)[i] = a;
}

// ---------------- launcher ----------------
extern "C" void kernel_launch(void* const* d_in, const int* in_sizes, int n_in,
                              void* d_out, int out_size) {
    (void)in_sizes; (void)n_in; (void)out_size;
    const float* x  = (const float*)d_in[0];
    const int*   ei = (const int*)  d_in[1];
    const float* Wg = (const float*)d_in[2];
    const float* bg = (const float*)d_in[3];
    const float* W1 = (const float*)d_in[4];
    const float* b1 = (const float*)d_in[5];
    const float* W2 = (const float*)d_in[6];
    const float* b2 = (const float*)d_in[7];
    float* out = (float*)d_out;

    __half* d_h    = nullptr; cudaGetSymbolAddress((void**)&d_h,    g_h);
    __half* d_gram = nullptr; cudaGetSymbolAddress((void**)&d_gram, g_gram);
    float*  d_z2p  = nullptr; cudaGetSymbolAddress((void**)&d_z2p,  g_z2p);
    __half* d_z2   = nullptr; cudaGetSymbolAddress((void**)&d_z2,   g_z2);
    float*  d_yp   = nullptr; cudaGetSymbolAddress((void**)&d_yp,   g_yp);

    const int smem2  = 2 * (64 * 36 + 32 * 136) * 4;  // h-GEMM NT=2: 53248 B
    const int smemf  = 3 * FSTAGE_B;                  // fp16 GEMM 3-stage: 66048 B
    cudaFuncSetAttribute(k_tgemm<2, 1, 1>, cudaFuncAttributeMaxDynamicSharedMemorySize, smem2);
    cudaFuncSetAttribute(k_fgemm, cudaFuncAttributeMaxDynamicSharedMemorySize, smemf);

    k_zero<<<20, 256>>>();
    k_fill<<<640, 256>>>(ei, ei + NE);
    k_dinv<<<20, 256>>>();
    // h = x @ Wg : M=5120 (80 tiles), N=128 (NT=2), K=256 (8 chunks), tf32 -> fp16 out
    k_tgemm<2, 1, 1><<<dim3(1, 80, 1), 256, smem2>>>(x, Wg, (float*)d_h,
                                                     TBLD, LAT, LAT, 8, 0);
    k_gather_z<<<640, 256>>>(bg);
    k_gram<<<NG, 256>>>();
    // GEMM1 (fp16): [64,6400] @ [6400,12800], 100 N-tiles x splitK 4 (200 chunks)
    k_fgemm<<<dim3(100, 1, SK1), 128, smemf>>>(d_gram, W1, d_z2p, N2, H1, H1,
                                               200, (long)NG * H1);
    k_relu_c<<<800, 256>>>(b1);
    // GEMM2 (fp16): [64,12800] @ [12800,6400], 50 N-tiles x splitK 8 (400 chunks)
    k_fgemm<<<dim3(50, 1, SK2), 128, smemf>>>(d_z2, W2, d_yp, H1, N2, N2,
                                              400, (long)NG * N2);
    k_sig_c<<<400, 256>>>(b2, out);
}

// round 14
// speedup vs baseline: 1.0819x; 1.0819x over previous
#include <cuda_runtime.h>
#include <cuda_fp16.h>
#include <cstdint>

#define NN 5120
#define NE 163840
#define TBLD 256
#define LAT 128
#define NG 64
#define NNEU 80
#define N2 6400
#define H1 12800

#define SK1 3     // GEMM1 split-K  (100 N-tiles x 3 = 300 CTAs, 2/SM)
#define SK2 6     // GEMM2 split-K  (50 N-tiles x 6 = 300 CTAs)

// ---------------- device scratch ----------------
__device__ int    g_deg[NN];
__device__ int    g_srclist[NN * 128];
__device__ float  g_dinv[NN];
__device__ __half g_h[NN * LAT];           // fp16 (x @ Wg)
__device__ __half g_z[NN * LAT];           // fp16 relu(GCN out)
__device__ __half g_gram[NG * N2];         // fp16 (A of GEMM1)
__device__ float  g_z2p[(size_t)SK1 * NG * H1];
__device__ __half g_z2[NG * H1];           // fp16 (A of GEMM2)
__device__ float  g_yp[(size_t)SK2 * NG * N2];

// ---------------- graph-side kernels ----------------
__global__ void k_zero() {
    int i = blockIdx.x * 256 + threadIdx.x;
    if (i < NN) g_deg[i] = 0;
}

__global__ void k_fill(const int* __restrict__ src, const int* __restrict__ dst) {
    int e = blockIdx.x * 256 + threadIdx.x;
    if (e >= NE) return;
    int d = dst[e];
    int slot = atomicAdd(&g_deg[d], 1);
    if (slot < 128) g_srclist[(d << 7) + slot] = src[e];
}

__global__ void k_dinv() {
    int i = blockIdx.x * 256 + threadIdx.x;
    if (i < NN) {
        int c = g_deg[i];
        g_dinv[i] = (c > 0) ? rsqrtf((float)c) : 0.0f;
    }
}

// one warp per node; h is fp16, 256 B/row (uint2 per lane = 4 halves)
__global__ void k_gather_z(const float* __restrict__ bg) {
    int w = (blockIdx.x * blockDim.x + threadIdx.x) >> 5;
    int lane = threadIdx.x & 31;
    if (w >= NN) return;
    int cnt = g_deg[w];
    if (cnt > 128) cnt = 128;
    const int* sl = g_srclist + (w << 7);
    float4 acc = make_float4(0.f, 0.f, 0.f, 0.f);
    #pragma unroll 4
    for (int e = 0; e < cnt; e++) {
        int s = sl[e];
        float wt = g_dinv[s];
        uint2 v = ((const uint2*)(g_h + ((size_t)s << 7)))[lane];
        float2 p0 = __half22float2(*(__half2*)&v.x);
        float2 p1 = __half22float2(*(__half2*)&v.y);
        acc.x += wt * p0.x; acc.y += wt * p0.y;
        acc.z += wt * p1.x; acc.w += wt * p1.y;
    }
    float dv = g_dinv[w];
    float4 bb = ((const float4*)bg)[lane];
    __half2 h0 = __floats2half2_rn(fmaxf(dv * acc.x + bb.x, 0.f),
                                   fmaxf(dv * acc.y + bb.y, 0.f));
    __half2 h1 = __floats2half2_rn(fmaxf(dv * acc.z + bb.z, 0.f),
                                   fmaxf(dv * acc.w + bb.w, 0.f));
    uint2 o; o.x = *(uint32_t*)&h0; o.y = *(uint32_t*)&h1;
    ((uint2*)(g_z + ((size_t)w << 7)))[lane] = o;
}

__global__ void k_gram() {
    __shared__ float zt[128][81];
    const int b = blockIdx.x;
    const int tid = threadIdx.x;
    #pragma unroll
    for (int i = 0; i < 10; i++) {
        int f = tid + i * 256;                 // 2560 = 80 rows x 32 quads
        int row = f >> 5, k4 = f & 31;
        uint2 v = ((const uint2*)(g_z + ((size_t)(b * NNEU + row) << 7)))[k4];
        float2 p0 = __half22float2(*(__half2*)&v.x);
        float2 p1 = __half22float2(*(__half2*)&v.y);
        zt[k4 * 4 + 0][row] = p0.x; zt[k4 * 4 + 1][row] = p0.y;
        zt[k4 * 4 + 2][row] = p1.x; zt[k4 * 4 + 3][row] = p1.y;
    }
    __syncthreads();
    const int tx = tid & 15, ty = tid >> 4;
    const int i0 = ty * 5, j0 = tx * 5;
    float acc[5][5];
    #pragma unroll
    for (int i = 0; i < 5; i++)
        #pragma unroll
        for (int j = 0; j < 5; j++) acc[i][j] = 0.f;
    #pragma unroll 4
    for (int k = 0; k < 128; k++) {
        float a[5], c[5];
        #pragma unroll
        for (int u = 0; u < 5; u++) { a[u] = zt[k][i0 + u]; c[u] = zt[k][j0 + u]; }
        #pragma unroll
        for (int i = 0; i < 5; i++)
            #pragma unroll
            for (int j = 0; j < 5; j++) acc[i][j] += a[i] * c[j];
    }
    __half* G = g_gram + b * N2;
    #pragma unroll
    for (int i = 0; i < 5; i++)
        #pragma unroll
        for (int j = 0; j < 5; j++)
            G[(i0 + i) * NNEU + j0 + j] = __float2half_rn(acc[i][j]);
}

// ---------------- mma helpers ----------------
__device__ __forceinline__ uint32_t smem_u32(const void* p) {
    return (uint32_t)__cvta_generic_to_shared(p);
}
__device__ __forceinline__ void cpa16(uint32_t dst, const void* src) {
    asm volatile("cp.async.cg.shared.global [%0], [%1], 16;" :: "r"(dst), "l"(src));
}
__device__ __forceinline__ uint32_t ldsu(uint32_t addr) {
    uint32_t v; asm volatile("ld.shared.b32 %0, [%1];" : "=r"(v) : "r"(addr)); return v;
}
__device__ __forceinline__ float ldsf(uint32_t addr) {
    float v; asm volatile("ld.shared.f32 %0, [%1];" : "=f"(v) : "r"(addr)); return v;
}
__device__ __forceinline__ uint32_t cvt2h(float hi, float lo) {
    uint32_t d;
    asm("cvt.rn.f16x2.f32 %0, %1, %2;" : "=r"(d) : "f"(hi), "f"(lo));
    return d;
}
__device__ __forceinline__ void hmma16(float* c, const uint32_t* a, uint32_t b0, uint32_t b1) {
    asm volatile(
        "mma.sync.aligned.m16n8k16.row.col.f32.f16.f16.f32 "
        "{%0,%1,%2,%3}, {%4,%5,%6,%7}, {%8,%9}, {%0,%1,%2,%3};"
        : "+f"(c[0]), "+f"(c[1]), "+f"(c[2]), "+f"(c[3])
        : "r"(a[0]), "r"(a[1]), "r"(a[2]), "r"(a[3]), "r"(b0), "r"(b1));
}
__device__ __forceinline__ void hmma(float* c, const uint32_t* a, uint32_t b0, uint32_t b1) {
    asm volatile(
        "mma.sync.aligned.m16n8k8.row.col.f32.tf32.tf32.f32 "
        "{%0,%1,%2,%3}, {%4,%5,%6,%7}, {%8,%9}, {%0,%1,%2,%3};"
        : "+f"(c[0]), "+f"(c[1]), "+f"(c[2]), "+f"(c[3])
        : "r"(a[0]), "r"(a[1]), "r"(a[2]), "r"(a[3]), "r"(b0), "r"(b1));
}

// ============ big-GEMM: fp16 A x fp32 B (cvt in regs), K-chunk 64, 2-stage ============
// 128 threads / 4 warps, tile M=64 x N=128; warp = 4 m16 x 4 n8; chunk = 4 k16 steps.
// A smem: half[64][72] (9216 B; frag banks 4g+t distinct).
// B smem: float[64][132] (33792 B; frag banks 8t+g distinct).
// Stage 43008 B; 2 stages = 86016 B -> 2 CTAs/SM.
#define FA_BYTES (64 * 144)
#define FSBW 132
#define FSTAGE_B (FA_BYTES + 64 * FSBW * 4)   // 43008 bytes

__global__ __launch_bounds__(128, 2) void k_fgemm(
    const __half* __restrict__ A, const float* __restrict__ B,
    float* __restrict__ C, int lda, int ldb, int ldc, int ctot, long csplit)
{
    extern __shared__ char smemc[];
    const int tid = threadIdx.x, wid = tid >> 5, lane = tid & 31;
    const int g = lane >> 2, t = lane & 3;
    const int n0 = blockIdx.x * 128;
    const int c0 = (int)((long)ctot * blockIdx.z / gridDim.z);
    const int c1 = (int)((long)ctot * (blockIdx.z + 1) / gridDim.z);
    const int nch = c1 - c0;                 // chunks of K=64
    const __half* Ab = A + (size_t)c0 * 64;
    const float* Bb = B + (size_t)c0 * 64 * ldb + n0;
    const uint32_t sb = smem_u32(smemc);
    const int nb = wid * 32;                 // warp n-base

    auto prefetch = [&](int ck, int buf) {
        uint32_t as = sb + buf * FSTAGE_B;
        uint32_t bs = as + FA_BYTES;
        const __half* Ag = Ab + ck * 64;
        #pragma unroll
        for (int q = 0; q < 4; q++) {        // A: 64 rows x 128B = 512 x 16B
            int idx = q * 128 + tid, r = idx >> 3, f = idx & 7;
            cpa16(as + r * 144 + f * 16, Ag + (size_t)r * lda + f * 8);
        }
        const float* Bg = Bb + (size_t)ck * 64 * ldb;
        #pragma unroll
        for (int q = 0; q < 16; q++) {       // B: 64 rows x 512B = 2048 x 16B
            int idx = q * 128 + tid, r = idx >> 5, f = idx & 31;
            cpa16(bs + r * (FSBW * 4) + f * 16, Bg + (size_t)r * ldb + f * 4);
        }
        asm volatile("cp.async.commit_group;" ::: "memory");
    };

    float acc[4][4][4];
    #pragma unroll
    for (int mt = 0; mt < 4; mt++)
        #pragma unroll
        for (int nt = 0; nt < 4; nt++)
            #pragma unroll
            for (int r = 0; r < 4; r++) acc[mt][nt][r] = 0.f;

    prefetch(0, 0);
    for (int it = 0; it < nch; it++) {
        if (it + 1 < nch) {
            prefetch(it + 1, (it + 1) & 1);
            asm volatile("cp.async.wait_group 1;" ::: "memory");
        } else {
            asm volatile("cp.async.wait_group 0;" ::: "memory");
        }
        __syncthreads();
        uint32_t as = sb + (it & 1) * FSTAGE_B;
        uint32_t bs = as + FA_BYTES;
        #pragma unroll
        for (int s = 0; s < 4; s++) {        // four k16 steps per chunk
            uint32_t a[4][4];
            #pragma unroll
            for (int mt = 0; mt < 4; mt++) {
                uint32_t r0 = as + (16 * mt + g) * 144 + s * 32 + t * 4;
                a[mt][0] = ldsu(r0);
                a[mt][1] = ldsu(r0 + 8 * 144);
                a[mt][2] = ldsu(r0 + 16);
                a[mt][3] = ldsu(r0 + 8 * 144 + 16);
            }
            #pragma unroll
            for (int nt = 0; nt < 4; nt++) {
                uint32_t col = nb + 8 * nt + g;
                uint32_t bo = bs + ((16 * s + 2 * t) * FSBW + col) * 4;
                float f0 = ldsf(bo);
                float f1 = ldsf(bo + FSBW * 4);
                float f2 = ldsf(bo + 8 * FSBW * 4);
                float f3 = ldsf(bo + 9 * FSBW * 4);
                uint32_t b0 = cvt2h(f1, f0);
                uint32_t b1 = cvt2h(f3, f2);
                #pragma unroll
                for (int mt = 0; mt < 4; mt++) hmma16(acc[mt][nt], a[mt], b0, b1);
            }
        }
        __syncthreads();
    }

    float* Cb = C + (size_t)blockIdx.z * csplit + n0 + nb;
    #pragma unroll
    for (int mt = 0; mt < 4; mt++) {
        #pragma unroll
        for (int nt = 0; nt < 4; nt++) {
            float* p0 = Cb + (size_t)(16 * mt + g) * ldc + 8 * nt + 2 * t;
            p0[0] = acc[mt][nt][0]; p0[1] = acc[mt][nt][1];
            float* p1 = p0 + 8 * (size_t)ldc;
            p1[0] = acc[mt][nt][2]; p1[1] = acc[mt][nt][3];
        }
    }
}

// ============ 8-warp tf32 template (h-GEMM only; H=1 -> fp16 output) ============
template<int NT, int RA, int H>
__global__ __launch_bounds__(256, 2) void k_tgemm(
    const float* __restrict__ A, const float* __restrict__ B,
    float* __restrict__ C, int lda, int ldb, int ldc, int ctot, long csplit)
{
    constexpr int BN   = 64 * NT;
    constexpr int SBW  = BN + 8;
    constexpr int ABUF = 64 * 36;
    constexpr int BUF  = ABUF + 32 * SBW;
    extern __shared__ float smem[];
    const int tid = threadIdx.x, wid = tid >> 5, lane = tid & 31;
    const int g = lane >> 2, t = lane & 3;
    const int n0 = blockIdx.x * BN;
    const int m0 = blockIdx.y * 64;
    const int c0 = (int)((long)ctot * blockIdx.z / gridDim.z);
    const int c1 = (int)((long)ctot * (blockIdx.z + 1) / gridDim.z);
    const int nch = c1 - c0;
    const float* Ab = A + (size_t)m0 * lda + (size_t)c0 * 32;
    const float* Bb = B + (size_t)c0 * 32 * ldb + n0;
    const uint32_t sb = smem_u32(smem);
    const int nbw = wid * 8 * NT;

    auto prefetch = [&](int ck, int buf) {
        uint32_t as = sb + buf * BUF * 4;
        uint32_t bs = as + ABUF * 4;
        const float* Ag = Ab + ck * 32;
        #pragma unroll
        for (int q = 0; q < 2; q++) {
            int idx = q * 256 + tid, r = idx >> 3, f = idx & 7;
            cpa16(as + (r * 36 + f * 4) * 4, Ag + (size_t)r * lda + f * 4);
        }
        const float* Bg = Bb + (size_t)ck * 32 * ldb;
        #pragma unroll
        for (int q = 0; q < 2 * NT; q++) {
            int idx = q * 256 + tid, r = idx / (16 * NT), f = idx % (16 * NT);
            cpa16(bs + (r * SBW + f * 4) * 4, Bg + (size_t)r * ldb + f * 4);
        }
        asm volatile("cp.async.commit_group;" ::: "memory");
    };

    float acc[4][NT][4];
    #pragma unroll
    for (int mt = 0; mt < 4; mt++)
        #pragma unroll
        for (int nt = 0; nt < NT; nt++)
            #pragma unroll
            for (int r = 0; r < 4; r++) acc[mt][nt][r] = 0.f;

    prefetch(0, 0);
    for (int it = 0; it < nch; it++) {
        if (it + 1 < nch) {
            prefetch(it + 1, (it + 1) & 1);
            asm volatile("cp.async.wait_group 1;" ::: "memory");
        } else {
            asm volatile("cp.async.wait_group 0;" ::: "memory");
        }
        __syncthreads();
        uint32_t as = sb + (it & 1) * BUF * 4;
        uint32_t bs = as + ABUF * 4;
        #pragma unroll
        for (int ks = 0; ks < 4; ks++) {
            uint32_t a[4][4];
            #pragma unroll
            for (int mt = 0; mt < 4; mt++) {
                uint32_t r0 = as + ((16 * mt + g) * 36 + 8 * ks + t) * 4;
                a[mt][0] = ldsu(r0);
                a[mt][1] = ldsu(r0 + 8 * 36 * 4);
                a[mt][2] = ldsu(r0 + 16);
                a[mt][3] = ldsu(r0 + 8 * 36 * 4 + 16);
                if (RA) {
                    a[mt][0] += 0x1000u; a[mt][1] += 0x1000u;
                    a[mt][2] += 0x1000u; a[mt][3] += 0x1000u;
                }
            }
            #pragma unroll
            for (int nt = 0; nt < NT; nt++) {
                uint32_t bo = bs + ((8 * ks + t) * SBW + nbw + 8 * nt + g) * 4;
                uint32_t b0 = ldsu(bo) + 0x1000u;
                uint32_t b1 = ldsu(bo + 4 * SBW * 4) + 0x1000u;
                #pragma unroll
                for (int mt = 0; mt < 4; mt++) hmma(acc[mt][nt], a[mt], b0, b1);
            }
        }
        __syncthreads();
    }

    #pragma unroll
    for (int mt = 0; mt < 4; mt++) {
        #pragma unroll
        for (int nt = 0; nt < NT; nt++) {
            if (H) {
                __half* Cb = (__half*)C + (size_t)blockIdx.z * csplit +
                             (size_t)m0 * ldc + n0 + nbw;
                __half2 h0 = __floats2half2_rn(acc[mt][nt][0], acc[mt][nt][1]);
                __half2 h1 = __floats2half2_rn(acc[mt][nt][2], acc[mt][nt][3]);
                *(__half2*)(Cb + (size_t)(16 * mt + g) * ldc + 8 * nt + 2 * t) = h0;
                *(__half2*)(Cb + (size_t)(16 * mt + g + 8) * ldc + 8 * nt + 2 * t) = h1;
            } else {
                float* Cb = C + (size_t)blockIdx.z * csplit + (size_t)m0 * ldc + n0 + nbw;
                float* p0 = Cb + (size_t)(16 * mt + g) * ldc + 8 * nt + 2 * t;
                p0[0] = acc[mt][nt][0]; p0[1] = acc[mt][nt][1];
                float* p1 = p0 + 8 * (size_t)ldc;
                p1[0] = acc[mt][nt][2]; p1[1] = acc[mt][nt][3];
            }
        }
    }
}

// combine SK1 GEMM1 partials + bias, relu -> fp16 g_z2
__global__ void k_relu_c(const float* __restrict__ b1) {
    int i = blockIdx.x * 256 + threadIdx.x;          // float4 idx < 204800
    const float4* P = (const float4*)g_z2p;
    float4 a = P[i];
    #pragma unroll
    for (int s = 1; s < SK1; s++) {
        float4 tv = P[(size_t)s * 204800 + i];
        a.x += tv.x; a.y += tv.y; a.z += tv.z; a.w += tv.w;
    }
    float4 bb = ((const float4*)b1)[i % 3200];
    __half2 h0 = __floats2half2_rn(fmaxf(a.x + bb.x, 0.f), fmaxf(a.y + bb.y, 0.f));
    __half2 h1 = __floats2half2_rn(fmaxf(a.z + bb.z, 0.f), fmaxf(a.w + bb.w, 0.f));
    ((__half2*)g_z2)[2 * i]     = h0;
    ((__half2*)g_z2)[2 * i + 1] = h1;
}

// combine SK2 GEMM2 partials + bias, sigmoid -> out
__global__ void k_sig_c(const float* __restrict__ b2, float* __restrict__ out) {
    int i = blockIdx.x * 256 + threadIdx.x;          // float4 idx < 102400
    const float4* P = (const float4*)g_yp;
    float4 a = P[i];
    #pragma unroll
    for (int p = 1; p < SK2; p++) {
        float4 tv = P[(size_t)p * 102400 + i];
        a.x += tv.x; a.y += tv.y; a.z += tv.z; a.w += tv.w;
    }
    float4 bb = ((const float4*)b2)[i % 1600];
    a.x = 1.f / (1.f + expf(-(a.x + bb.x)));
    a.y = 1.f / (1.f + expf(-(a.y + bb.y)));
    a.z = 1.f / (1.f + expf(-(a.z + bb.z)));
    a.w = 1.f / (1.f + expf(-(a.w + bb.w)));
    ((float4*)out)[i] = a;
}

// ---------------- launcher ----------------
extern "C" void kernel_launch(void* const* d_in, const int* in_sizes, int n_in,
                              void* d_out, int out_size) {
    (void)in_sizes; (void)n_in; (void)out_size;
    const float* x  = (const float*)d_in[0];
    const int*   ei = (const int*)  d_in[1];
    const float* Wg = (const float*)d_in[2];
    const float* bg = (const float*)d_in[3];
    const float* W1 = (const float*)d_in[4];
    const float* b1 = (const float*)d_in[5];
    const float* W2 = (const float*)d_in[6];
    const float* b2 = (const float*)d_in[7];
    float* out = (float*)d_out;

    __half* d_h    = nullptr; cudaGetSymbolAddress((void**)&d_h,    g_h);
    __half* d_gram = nullptr; cudaGetSymbolAddress((void**)&d_gram, g_gram);
    float*  d_z2p  = nullptr; cudaGetSymbolAddress((void**)&d_z2p,  g_z2p);
    __half* d_z2   = nullptr; cudaGetSymbolAddress((void**)&d_z2,   g_z2);
    float*  d_yp   = nullptr; cudaGetSymbolAddress((void**)&d_yp,   g_yp);

    const int smem2  = 2 * (64 * 36 + 32 * 136) * 4;  // h-GEMM NT=2: 53248 B
    const int smemf  = 2 * FSTAGE_B;                  // fp16 GEMM: 86016 B
    cudaFuncSetAttribute(k_tgemm<2, 1, 1>, cudaFuncAttributeMaxDynamicSharedMemorySize, smem2);
    cudaFuncSetAttribute(k_fgemm, cudaFuncAttributeMaxDynamicSharedMemorySize, smemf);

    k_zero<<<20, 256>>>();
    k_fill<<<640, 256>>>(ei, ei + NE);
    k_dinv<<<20, 256>>>();
    // h = x @ Wg : M=5120 (80 tiles), N=128 (NT=2), K=256 (8 chunks), tf32 -> fp16 out
    k_tgemm<2, 1, 1><<<dim3(1, 80, 1), 256, smem2>>>(x, Wg, (float*)d_h,
                                                     TBLD, LAT, LAT, 8, 0);
    k_gather_z<<<640, 256>>>(bg);
    k_gram<<<NG, 256>>>();
    // GEMM1 (fp16): [64,6400] @ [6400,12800], 100 N-tiles x splitK 3 (100 chunks of 64)
    k_fgemm<<<dim3(100, 1, SK1), 128, smemf>>>(d_gram, W1, d_z2p, N2, H1, H1,
                                               100, (long)NG * H1);
    k_relu_c<<<800, 256>>>(b1);
    // GEMM2 (fp16): [64,12800] @ [12800,6400], 50 N-tiles x splitK 6 (200 chunks of 64)
    k_fgemm<<<dim3(50, 1, SK2), 128, smemf>>>(d_z2, W2, d_yp, H1, N2, N2,
                                              200, (long)NG * N2);
    k_sig_c<<<400, 256>>>(b2, out);
}